// round 14
// baseline (speedup 1.0000x reference)
#include <cuda_runtime.h>
#include <cuda_fp16.h>
#include <cstdint>

#define NT    256
#define GRID  148
#define DTf   0.05f
#define MAXTILES 1024

// ---------------- Tsit5 tableau ----------------
__constant__ float c_A[6][5] = {
    {0.f, 0.f, 0.f, 0.f, 0.f},
    {0.161f, 0.f, 0.f, 0.f, 0.f},
    {-0.008480655492356989f, 0.335480655492357f, 0.f, 0.f, 0.f},
    {2.8971530571054935f, -6.359448489975075f, 4.3622954328695815f, 0.f, 0.f},
    {5.325864828439257f, -11.748883564062828f, 7.4955393428898365f, -0.09249506636175525f, 0.f},
    {5.86145544294642f, -12.92096931784711f, 8.159367898576159f, -0.071584973281401f, -0.028269050394068383f},
};
__constant__ float c_Bc[6] = {
    0.09646076681806523f, 0.01f, 0.4798896504144996f,
    1.379008574103742f, -3.290069515436081f, 2.324710524099774f
};

// k scratch: [tile][stage][row(128)][colpair(32)] f16x2 (L2-resident working set)
__device__ uint32_t g_k[(size_t)MAXTILES * 5 * 128 * 32];
// W1 B-fragments in global (L2-hot, shared by all CTAs):
//   pairs:   [p(2)][nfg(32)][lane(32)] x 16B = 32768 B
//   singles: [nfg(32)][lane(32)] x 8B        =  8192 B
__device__ __align__(16) unsigned char g_w1c[40960];

// ---------------- SMEM layout (bytes) ----------------
// h buffer (h1/h2 staging, A-frag layout): [mw(4)][Mh(2)][ks2(16)][lane(32)] x 16B
#define OH   0          // 65536
#define OW2  65536      // [p(8)][nfg(32)][lane] x 16B = 131072
#define OW3  196608     // [p(8)][nfg(8)][lane] x 16B  = 32768
#define OB1  229376     // 256 f32
#define OB2  230400     // 256 f32
#define OB3  231424     // 64 f32
#define SMEM_BYTES 231680

// ---------------- helpers ----------------
__device__ __forceinline__ uint32_t packh(float lo, float hi) {
    uint32_t r; asm("cvt.rn.f16x2.f32 %0, %1, %2;" : "=r"(r) : "f"(hi), "f"(lo)); return r;
}
__device__ __forceinline__ uint32_t packh2(float2 v) { return packh(v.x, v.y); }
__device__ __forceinline__ float2 unpackh(uint32_t v) {
    __half2 h = *reinterpret_cast<__half2*>(&v);
    return __half22float2(h);
}
__device__ __forceinline__ float tanh_fast(float x) {
    float y; asm("tanh.approx.f32 %0, %1;" : "=f"(y) : "f"(x)); return y;
}
__device__ __forceinline__ float silu(float x) {
    float t = tanh_fast(0.5f * x);
    return fmaf(x, 0.5f * t, 0.5f * x);
}
__device__ __forceinline__ void mma_f16h(uint32_t* c, const uint32_t* a, uint32_t b0, uint32_t b1) {
    asm volatile(
        "mma.sync.aligned.m16n8k16.row.col.f16.f16.f16.f16 "
        "{%0,%1},{%2,%3,%4,%5},{%6,%7},{%0,%1};"
        : "+r"(c[0]), "+r"(c[1])
        : "r"(a[0]), "r"(a[1]), "r"(a[2]), "r"(a[3]), "r"(b0), "r"(b1));
}

extern __shared__ char sm[];

__global__ void __launch_bounds__(NT, 1)
tsit5_mma_kernel(const float* __restrict__ obs, const float* __restrict__ act,
                 const float* __restrict__ gW1, const float* __restrict__ gb1,
                 const float* __restrict__ gW2, const float* __restrict__ gb2,
                 const float* __restrict__ gW3, const float* __restrict__ gb3,
                 float* __restrict__ out, int ntiles)
{
    const int tid = threadIdx.x;

    // ---- weight conversion: W1 -> global frag array, W2/W3 -> SMEM frags ----
    for (int idx = tid; idx < 80 * 256; idx += NT) {
        int k = idx >> 8, n = idx & 255;
        int lane = (n & 7) * 4 + ((k & 7) >> 1);
        int kb = (((k >> 3) & 1) << 2) + ((k & 1) << 1);
        int ks = k >> 4, nfg = n >> 3;
        int off = (ks < 4) ? ((((ks >> 1) * 32 + nfg) * 32 + lane) * 16 + (ks & 1) * 8 + kb)
                           : (32768 + (nfg * 32 + lane) * 8 + kb);
        *(__half*)(g_w1c + off) = __float2half(gW1[idx]);
    }
    for (int idx = tid; idx < 256 * 256; idx += NT) {
        int k = idx >> 8, n = idx & 255;
        int lane = (n & 7) * 4 + ((k & 7) >> 1);
        int kb = (((k >> 3) & 1) << 2) + ((k & 1) << 1);
        int ks = k >> 4, p = ks >> 1, nfg = n >> 3;
        int off = OW2 + ((p * 32 + nfg) * 32 + lane) * 16 + (ks & 1) * 8 + kb;
        *(__half*)(sm + off) = __float2half(gW2[idx]);
    }
    for (int idx = tid; idx < 256 * 64; idx += NT) {
        int k = idx >> 6, n = idx & 63;
        int lane = (n & 7) * 4 + ((k & 7) >> 1);
        int kb = (((k >> 3) & 1) << 2) + ((k & 1) << 1);
        int ks = k >> 4, p = ks >> 1, nfg = n >> 3;
        int off = OW3 + ((p * 8 + nfg) * 32 + lane) * 16 + (ks & 1) * 8 + kb;
        *(__half*)(sm + off) = __float2half(gW3[idx]);
    }
    for (int i = tid; i < 256; i += NT) {
        ((float*)(sm + OB1))[i] = gb1[i];
        ((float*)(sm + OB2))[i] = gb2[i];
    }
    for (int i = tid; i < 64; i += NT) ((float*)(sm + OB3))[i] = gb3[i];
    __syncthreads();

    const float* B1 = (const float*)(sm + OB1);
    const float* B2 = (const float*)(sm + OB2);
    const float* B3 = (const float*)(sm + OB3);

    const int w  = tid >> 5, l = tid & 31;
    const int h  = w >> 2;           // N-half (0: cols 0-127, 1: cols 128-255)
    const int mw = w & 3;            // row group (32 rows each)
    const int mrow0 = mw * 32;
    const int rl = l >> 2;
    const int lp = l & 3;
    const int cp = lp * 2;

    const uint4* w1q = (const uint4*)g_w1c;
    const uint2* w1s = (const uint2*)(g_w1c + 32768);
    const uint4* w2q = (const uint4*)(sm + OW2);
    const uint4* w3q = (const uint4*)(sm + OW3);
    // h buffer lane base: group stride 32 uint4; groups indexed (Mh*16+ks2); mw block = 1024 uint4
    uint4* hb = (uint4*)(sm + OH) + mw * 1024 + l;

    for (int tile = blockIdx.x; tile < ntiles; tile += GRID) {
        const long base = (long)tile * 128;
        uint32_t* ktile = g_k + (size_t)tile * 5 * 4096;   // stage stride 4096 u32

        // action A-frags (persistent per tile)
        uint32_t xact[2][4];
        #pragma unroll
        for (int Mh = 0; Mh < 2; Mh++) {
            const float* aa = act + (base + mrow0 + 16 * Mh + rl) * 16;
            xact[Mh][0] = packh2(*(const float2*)(aa + cp));
            xact[Mh][1] = packh2(*(const float2*)(aa + 128 + cp));
            xact[Mh][2] = packh2(*(const float2*)(aa + 8 + cp));
            xact[Mh][3] = packh2(*(const float2*)(aa + 128 + 8 + cp));
        }

        #pragma unroll 1
        for (int st = 0; st < 6; st++) {
            __syncthreads();   // S_A: prev-stage k STGs + buffer reads complete

            // ---- x-build: fp32 y0 + dt * sum_j a[st][j] * k_j (k from g_k, L2) ----
            uint32_t xa[2][4][4];
            #pragma unroll
            for (int Mh = 0; Mh < 2; Mh++) {
                const float* ya = obs + (base + mrow0 + 16 * Mh + rl) * 64;
                const float* yb = ya + 512;
                const uint32_t* kr  = ktile + (mrow0 + 16 * Mh + rl) * 32;
                const uint32_t* kr8 = kr + 256;
                #pragma unroll
                for (int ks = 0; ks < 4; ks++) {
                    float2 v0 = *(const float2*)(ya + 16 * ks + cp);
                    float2 v1 = *(const float2*)(yb + 16 * ks + cp);
                    float2 v2 = *(const float2*)(ya + 16 * ks + 8 + cp);
                    float2 v3 = *(const float2*)(yb + 16 * ks + 8 + cp);
                    #pragma unroll
                    for (int j = 0; j < 5; j++)
                        if (j < st) {
                            float a = DTf * c_A[st][j];
                            float2 t;
                            t = unpackh(kr [j * 4096 + 8 * ks + lp]);     v0.x = fmaf(a, t.x, v0.x); v0.y = fmaf(a, t.y, v0.y);
                            t = unpackh(kr8[j * 4096 + 8 * ks + lp]);     v1.x = fmaf(a, t.x, v1.x); v1.y = fmaf(a, t.y, v1.y);
                            t = unpackh(kr [j * 4096 + 8 * ks + 4 + lp]); v2.x = fmaf(a, t.x, v2.x); v2.y = fmaf(a, t.y, v2.y);
                            t = unpackh(kr8[j * 4096 + 8 * ks + 4 + lp]); v3.x = fmaf(a, t.x, v3.x); v3.y = fmaf(a, t.y, v3.y);
                        }
                    xa[Mh][ks][0] = packh2(v0);
                    xa[Mh][ks][1] = packh2(v1);
                    xa[Mh][ks][2] = packh2(v2);
                    xa[Mh][ks][3] = packh2(v3);
                }
            }

            // ---- GEMM1: h1(32 rows x 128 cols per warp) = silu(X @ W1 + b1) ----
            uint32_t acc1[2][16][2];
            #pragma unroll
            for (int nf = 0; nf < 16; nf++) {
                uint32_t bh = packh2(*(const float2*)(B1 + 128 * h + 8 * nf + cp));
                acc1[0][nf][0] = bh; acc1[0][nf][1] = bh;
                acc1[1][nf][0] = bh; acc1[1][nf][1] = bh;
            }
            #pragma unroll
            for (int p = 0; p < 2; p++)
                #pragma unroll
                for (int nf = 0; nf < 16; nf++) {
                    uint4 bb = w1q[(p * 32 + 16 * h + nf) * 32 + l];
                    #pragma unroll
                    for (int Mh = 0; Mh < 2; Mh++) {
                        mma_f16h(acc1[Mh][nf], xa[Mh][2 * p],     bb.x, bb.y);
                        mma_f16h(acc1[Mh][nf], xa[Mh][2 * p + 1], bb.z, bb.w);
                    }
                }
            #pragma unroll
            for (int nf = 0; nf < 16; nf++) {
                uint2 bb = w1s[(16 * h + nf) * 32 + l];
                #pragma unroll
                for (int Mh = 0; Mh < 2; Mh++)
                    mma_f16h(acc1[Mh][nf], xact[Mh], bb.x, bb.y);
            }
            // silu -> h buffer (A-frag layout; STS.128, conflict-free)
            #pragma unroll
            for (int Mh = 0; Mh < 2; Mh++)
                #pragma unroll
                for (int nfp = 0; nfp < 8; nfp++) {
                    float2 a0 = unpackh(acc1[Mh][2 * nfp][0]);
                    float2 a1 = unpackh(acc1[Mh][2 * nfp][1]);
                    float2 a2 = unpackh(acc1[Mh][2 * nfp + 1][0]);
                    float2 a3 = unpackh(acc1[Mh][2 * nfp + 1][1]);
                    uint4 val;
                    val.x = packh(silu(a0.x), silu(a0.y));
                    val.y = packh(silu(a1.x), silu(a1.y));
                    val.z = packh(silu(a2.x), silu(a2.y));
                    val.w = packh(silu(a3.x), silu(a3.y));
                    hb[(Mh * 16 + 8 * h + nfp) * 32] = val;
                }
            __syncthreads();   // S_B: h1 writes -> reads

            // ---- GEMM2: full-K from h buffer, N-half of W2 ----
            uint32_t acc2[2][16][2];
            #pragma unroll
            for (int nf = 0; nf < 16; nf++) {
                uint32_t bh = packh2(*(const float2*)(B2 + 128 * h + 8 * nf + cp));
                acc2[0][nf][0] = bh; acc2[0][nf][1] = bh;
                acc2[1][nf][0] = bh; acc2[1][nf][1] = bh;
            }
            #pragma unroll 2
            for (int p = 0; p < 8; p++) {
                uint4 A0[2], A1[2];
                #pragma unroll
                for (int Mh = 0; Mh < 2; Mh++) {
                    A0[Mh] = hb[(Mh * 16 + 2 * p) * 32];
                    A1[Mh] = hb[(Mh * 16 + 2 * p + 1) * 32];
                }
                #pragma unroll
                for (int nf = 0; nf < 16; nf++) {
                    uint4 bb = w2q[(p * 32 + 16 * h + nf) * 32 + l];
                    #pragma unroll
                    for (int Mh = 0; Mh < 2; Mh++) {
                        mma_f16h(acc2[Mh][nf], (const uint32_t*)&A0[Mh], bb.x, bb.y);
                        mma_f16h(acc2[Mh][nf], (const uint32_t*)&A1[Mh], bb.z, bb.w);
                    }
                }
            }
            __syncthreads();   // S_C: h1 reads -> h2 writes
            #pragma unroll
            for (int Mh = 0; Mh < 2; Mh++)
                #pragma unroll
                for (int nfp = 0; nfp < 8; nfp++) {
                    float2 a0 = unpackh(acc2[Mh][2 * nfp][0]);
                    float2 a1 = unpackh(acc2[Mh][2 * nfp][1]);
                    float2 a2 = unpackh(acc2[Mh][2 * nfp + 1][0]);
                    float2 a3 = unpackh(acc2[Mh][2 * nfp + 1][1]);
                    uint4 val;
                    val.x = packh(silu(a0.x), silu(a0.y));
                    val.y = packh(silu(a1.x), silu(a1.y));
                    val.z = packh(silu(a2.x), silu(a2.y));
                    val.w = packh(silu(a3.x), silu(a3.y));
                    hb[(Mh * 16 + 8 * h + nfp) * 32] = val;
                }
            __syncthreads();   // S_D: h2 writes -> reads

            // ---- GEMM3: full-K from h buffer, N-half (32 cols) of W3 ----
            uint32_t acc3[2][4][2];
            #pragma unroll
            for (int nf = 0; nf < 4; nf++) {
                uint32_t bh = packh2(*(const float2*)(B3 + 32 * h + 8 * nf + cp));
                acc3[0][nf][0] = bh; acc3[0][nf][1] = bh;
                acc3[1][nf][0] = bh; acc3[1][nf][1] = bh;
            }
            #pragma unroll 2
            for (int p = 0; p < 8; p++) {
                uint4 A0[2], A1[2];
                #pragma unroll
                for (int Mh = 0; Mh < 2; Mh++) {
                    A0[Mh] = hb[(Mh * 16 + 2 * p) * 32];
                    A1[Mh] = hb[(Mh * 16 + 2 * p + 1) * 32];
                }
                #pragma unroll
                for (int nf = 0; nf < 4; nf++) {
                    uint4 bb = w3q[(p * 8 + 4 * h + nf) * 32 + l];
                    #pragma unroll
                    for (int Mh = 0; Mh < 2; Mh++) {
                        mma_f16h(acc3[Mh][nf], (const uint32_t*)&A0[Mh], bb.x, bb.y);
                        mma_f16h(acc3[Mh][nf], (const uint32_t*)&A1[Mh], bb.z, bb.w);
                    }
                }
            }

            // ---- epilogue ----
            if (st < 5) {
                // k -> g_k [row][colpair] (readable by both N-halves next stage)
                #pragma unroll
                for (int Mh = 0; Mh < 2; Mh++) {
                    uint32_t* kw = ktile + st * 4096 + (mrow0 + 16 * Mh + rl) * 32 + 16 * h + lp;
                    #pragma unroll
                    for (int nf = 0; nf < 4; nf++) {
                        kw[4 * nf]       = acc3[Mh][nf][0];
                        kw[4 * nf + 256] = acc3[Mh][nf][1];
                    }
                }
            } else {
                const float d5 = DTf * c_Bc[5];
                #pragma unroll
                for (int Mh = 0; Mh < 2; Mh++) {
                    const long r0 = base + mrow0 + 16 * Mh + rl;
                    const float* ya = obs + r0 * 64 + 32 * h;
                    float* oa = out + r0 * 64 + 32 * h;
                    const uint32_t* kr = ktile + (mrow0 + 16 * Mh + rl) * 32 + 16 * h + lp;
                    #pragma unroll
                    for (int nf = 0; nf < 4; nf++) {
                        float2 y0v = *(const float2*)(ya + 8 * nf + cp);
                        float2 y1v = *(const float2*)(ya + 512 + 8 * nf + cp);
                        float2 k5a = unpackh(acc3[Mh][nf][0]);
                        float2 k5b = unpackh(acc3[Mh][nf][1]);
                        float o00 = fmaf(d5, k5a.x, y0v.x), o01 = fmaf(d5, k5a.y, y0v.y);
                        float o10 = fmaf(d5, k5b.x, y1v.x), o11 = fmaf(d5, k5b.y, y1v.y);
                        #pragma unroll
                        for (int j = 0; j < 5; j++) {
                            float d = DTf * c_Bc[j];
                            float2 ta = unpackh(kr[j * 4096 + 4 * nf]);
                            float2 tb = unpackh(kr[j * 4096 + 4 * nf + 256]);
                            o00 = fmaf(d, ta.x, o00); o01 = fmaf(d, ta.y, o01);
                            o10 = fmaf(d, tb.x, o10); o11 = fmaf(d, tb.y, o11);
                        }
                        *(float2*)(oa + 8 * nf + cp) = make_float2(o00, o01);
                        *(float2*)(oa + 512 + 8 * nf + cp) = make_float2(o10, o11);
                    }
                }
            }
        }
    }
}

extern "C" void kernel_launch(void* const* d_in, const int* in_sizes, int n_in,
                              void* d_out, int out_size)
{
    const float* obs = (const float*)d_in[0];
    const float* act = (const float*)d_in[1];
    const float* W1  = (const float*)d_in[2];
    const float* b1  = (const float*)d_in[3];
    const float* W2  = (const float*)d_in[4];
    const float* b2  = (const float*)d_in[5];
    const float* W3  = (const float*)d_in[6];
    const float* b3  = (const float*)d_in[7];
    float* out = (float*)d_out;

    const int batch  = in_sizes[0] / 64;
    int ntiles = batch / 128;
    if (ntiles > MAXTILES) ntiles = MAXTILES;

    cudaFuncSetAttribute(tsit5_mma_kernel,
                         cudaFuncAttributeMaxDynamicSharedMemorySize, SMEM_BYTES);

    tsit5_mma_kernel<<<GRID, NT, SMEM_BYTES>>>(obs, act, W1, b1, W2, b2, W3, b3, out, ntiles);
}

// round 15
// speedup vs baseline: 1.0121x; 1.0121x over previous
#include <cuda_runtime.h>
#include <cuda_fp16.h>
#include <cstdint>

#define NT    512
#define GRID  148
#define DTf   0.05f
#define MAXTILES 1024

// ---------------- Tsit5 tableau ----------------
__constant__ float c_A[6][5] = {
    {0.f, 0.f, 0.f, 0.f, 0.f},
    {0.161f, 0.f, 0.f, 0.f, 0.f},
    {-0.008480655492356989f, 0.335480655492357f, 0.f, 0.f, 0.f},
    {2.8971530571054935f, -6.359448489975075f, 4.3622954328695815f, 0.f, 0.f},
    {5.325864828439257f, -11.748883564062828f, 7.4955393428898365f, -0.09249506636175525f, 0.f},
    {5.86145544294642f, -12.92096931784711f, 8.159367898576159f, -0.071584973281401f, -0.028269050394068383f},
};
__constant__ float c_Bc[6] = {
    0.09646076681806523f, 0.01f, 0.4798896504144996f,
    1.379008574103742f, -3.290069515436081f, 2.324710524099774f
};

// k scratch: [tile][stage][row(128)][colpair(32)] f16x2 (L1/L2-hot working set)
__device__ uint32_t g_k[(size_t)MAXTILES * 5 * 128 * 32];
// W1 B-fragments in global (L1-cached):
//   pairs:   [p(2)][nfg(32)][lane(32)] x 16B = 32768 B
//   singles: [nfg(32)][lane(32)] x 8B        =  8192 B
__device__ __align__(16) unsigned char g_w1c[40960];

// ---------------- SMEM layout (bytes) ----------------
// h buffer (h1/h2 staging, A-frag layout): [mw(8)][g(16)][lane(32)] x 16B = 65536
#define OH   0
#define OW2  65536      // [p(8)][nfg(32)][lane] x 16B = 131072
#define OW3  196608     // [p(8)][nfg(8)][lane] x 16B  = 32768
#define OB1  229376     // 256 f32
#define OB2  230400     // 256 f32
#define OB3  231424     // 64 f32
#define SMEM_BYTES 231680

// ---------------- helpers ----------------
__device__ __forceinline__ uint32_t packh(float lo, float hi) {
    uint32_t r; asm("cvt.rn.f16x2.f32 %0, %1, %2;" : "=r"(r) : "f"(hi), "f"(lo)); return r;
}
__device__ __forceinline__ uint32_t packh2(float2 v) { return packh(v.x, v.y); }
__device__ __forceinline__ float2 unpackh(uint32_t v) {
    __half2 h = *reinterpret_cast<__half2*>(&v);
    return __half22float2(h);
}
__device__ __forceinline__ float tanh_fast(float x) {
    float y; asm("tanh.approx.f32 %0, %1;" : "=f"(y) : "f"(x)); return y;
}
__device__ __forceinline__ float silu(float x) {
    float t = tanh_fast(0.5f * x);
    return fmaf(x, 0.5f * t, 0.5f * x);
}
__device__ __forceinline__ void mma_f16h(uint32_t* c, const uint32_t* a, uint32_t b0, uint32_t b1) {
    asm volatile(
        "mma.sync.aligned.m16n8k16.row.col.f16.f16.f16.f16 "
        "{%0,%1},{%2,%3,%4,%5},{%6,%7},{%0,%1};"
        : "+r"(c[0]), "+r"(c[1])
        : "r"(a[0]), "r"(a[1]), "r"(a[2]), "r"(a[3]), "r"(b0), "r"(b1));
}

extern __shared__ char sm[];

__global__ void __launch_bounds__(NT, 1)
tsit5_mma_kernel(const float* __restrict__ obs, const float* __restrict__ act,
                 const float* __restrict__ gW1, const float* __restrict__ gb1,
                 const float* __restrict__ gW2, const float* __restrict__ gb2,
                 const float* __restrict__ gW3, const float* __restrict__ gb3,
                 float* __restrict__ out, int ntiles)
{
    const int tid = threadIdx.x;

    // ---- weight conversion: W1 -> global frags, W2/W3 -> SMEM frags ----
    for (int idx = tid; idx < 80 * 256; idx += NT) {
        int k = idx >> 8, n = idx & 255;
        int lane = (n & 7) * 4 + ((k & 7) >> 1);
        int kb = (((k >> 3) & 1) << 2) + ((k & 1) << 1);
        int ks = k >> 4, nfg = n >> 3;
        int off = (ks < 4) ? ((((ks >> 1) * 32 + nfg) * 32 + lane) * 16 + (ks & 1) * 8 + kb)
                           : (32768 + (nfg * 32 + lane) * 8 + kb);
        *(__half*)(g_w1c + off) = __float2half(gW1[idx]);
    }
    for (int idx = tid; idx < 256 * 256; idx += NT) {
        int k = idx >> 8, n = idx & 255;
        int lane = (n & 7) * 4 + ((k & 7) >> 1);
        int kb = (((k >> 3) & 1) << 2) + ((k & 1) << 1);
        int ks = k >> 4, p = ks >> 1, nfg = n >> 3;
        *(__half*)(sm + OW2 + ((p * 32 + nfg) * 32 + lane) * 16 + (ks & 1) * 8 + kb) =
            __float2half(gW2[idx]);
    }
    for (int idx = tid; idx < 256 * 64; idx += NT) {
        int k = idx >> 6, n = idx & 63;
        int lane = (n & 7) * 4 + ((k & 7) >> 1);
        int kb = (((k >> 3) & 1) << 2) + ((k & 1) << 1);
        int ks = k >> 4, p = ks >> 1, nfg = n >> 3;
        *(__half*)(sm + OW3 + ((p * 8 + nfg) * 32 + lane) * 16 + (ks & 1) * 8 + kb) =
            __float2half(gW3[idx]);
    }
    for (int i = tid; i < 256; i += NT) {
        ((float*)(sm + OB1))[i] = gb1[i];
        ((float*)(sm + OB2))[i] = gb2[i];
    }
    for (int i = tid; i < 64; i += NT) ((float*)(sm + OB3))[i] = gb3[i];
    __syncthreads();

    const float* B1 = (const float*)(sm + OB1);
    const float* B2 = (const float*)(sm + OB2);
    const float* B3 = (const float*)(sm + OB3);

    const int w  = tid >> 5, l = tid & 31;
    const int h  = w >> 3;           // N-half: 0 -> cols 0-127, 1 -> cols 128-255
    const int mw = w & 7;            // M-group: 16 rows each (128-row tile)
    const int mrow0 = mw * 16;
    const int rl = l >> 2;
    const int lp = l & 3;
    const int cp = lp * 2;

    const uint4* w1q = (const uint4*)g_w1c;
    const uint2* w1s = (const uint2*)(g_w1c + 32768);
    const uint4* w2q = (const uint4*)(sm + OW2);
    const uint4* w3q = (const uint4*)(sm + OW3);
    uint4* hb = (uint4*)(sm + OH) + mw * 512 + l;   // [g(16)]*32 stride

    for (int tile = blockIdx.x; tile < ntiles; tile += GRID) {
        const long base = (long)tile * 128;
        uint32_t* ktile = g_k + (size_t)tile * 5 * 4096;   // stage stride 4096 u32

        // action A-frags (persistent per tile)
        uint32_t xact[4];
        {
            const float* aa = act + (base + mrow0 + rl) * 16;
            xact[0] = packh2(*(const float2*)(aa + cp));
            xact[1] = packh2(*(const float2*)(aa + 128 + cp));
            xact[2] = packh2(*(const float2*)(aa + 8 + cp));
            xact[3] = packh2(*(const float2*)(aa + 128 + 8 + cp));
        }

        #pragma unroll 1
        for (int st = 0; st < 6; st++) {
            __syncthreads();   // S_A: prev-stage k writes + hb reads complete

            // ---- x-build: fp32 y0 + dt * sum_j a[st][j]*k_j ----
            uint32_t xa[4][4];
            {
                const float* ya = obs + (base + mrow0 + rl) * 64;
                const float* yb = ya + 512;
                const uint32_t* kr  = ktile + (mrow0 + rl) * 32;
                const uint32_t* kr8 = kr + 256;
                #pragma unroll
                for (int ks = 0; ks < 4; ks++) {
                    float2 v0 = *(const float2*)(ya + 16 * ks + cp);
                    float2 v1 = *(const float2*)(yb + 16 * ks + cp);
                    float2 v2 = *(const float2*)(ya + 16 * ks + 8 + cp);
                    float2 v3 = *(const float2*)(yb + 16 * ks + 8 + cp);
                    #pragma unroll
                    for (int j = 0; j < 5; j++)
                        if (j < st) {
                            float a = DTf * c_A[st][j];
                            float2 t;
                            t = unpackh(kr [j * 4096 + 8 * ks + lp]);     v0.x = fmaf(a, t.x, v0.x); v0.y = fmaf(a, t.y, v0.y);
                            t = unpackh(kr8[j * 4096 + 8 * ks + lp]);     v1.x = fmaf(a, t.x, v1.x); v1.y = fmaf(a, t.y, v1.y);
                            t = unpackh(kr [j * 4096 + 8 * ks + 4 + lp]); v2.x = fmaf(a, t.x, v2.x); v2.y = fmaf(a, t.y, v2.y);
                            t = unpackh(kr8[j * 4096 + 8 * ks + 4 + lp]); v3.x = fmaf(a, t.x, v3.x); v3.y = fmaf(a, t.y, v3.y);
                        }
                    xa[ks][0] = packh2(v0);
                    xa[ks][1] = packh2(v1);
                    xa[ks][2] = packh2(v2);
                    xa[ks][3] = packh2(v3);
                }
            }

            // ---- GEMM1: h1 (16 rows x 128 cols) = silu(X @ W1 + b1) ----
            {
                uint32_t acc1[16][2];
                #pragma unroll
                for (int nf = 0; nf < 16; nf++) {
                    uint32_t bh = packh2(*(const float2*)(B1 + 128 * h + 8 * nf + cp));
                    acc1[nf][0] = bh; acc1[nf][1] = bh;
                }
                #pragma unroll
                for (int p = 0; p < 2; p++)
                    #pragma unroll
                    for (int nf = 0; nf < 16; nf++) {
                        uint4 bb = w1q[(p * 32 + 16 * h + nf) * 32 + l];
                        mma_f16h(acc1[nf], xa[2 * p],     bb.x, bb.y);
                        mma_f16h(acc1[nf], xa[2 * p + 1], bb.z, bb.w);
                    }
                #pragma unroll
                for (int nf = 0; nf < 16; nf++) {
                    uint2 bb = w1s[(16 * h + nf) * 32 + l];
                    mma_f16h(acc1[nf], xact, bb.x, bb.y);
                }
                // silu -> h buffer (warp writes its N-half groups)
                #pragma unroll
                for (int nfp = 0; nfp < 8; nfp++) {
                    float2 a0 = unpackh(acc1[2 * nfp][0]);
                    float2 a1 = unpackh(acc1[2 * nfp][1]);
                    float2 a2 = unpackh(acc1[2 * nfp + 1][0]);
                    float2 a3 = unpackh(acc1[2 * nfp + 1][1]);
                    uint4 val;
                    val.x = packh(silu(a0.x), silu(a0.y));
                    val.y = packh(silu(a1.x), silu(a1.y));
                    val.z = packh(silu(a2.x), silu(a2.y));
                    val.w = packh(silu(a3.x), silu(a3.y));
                    hb[(8 * h + nfp) * 32] = val;
                }
            }
            __syncthreads();   // S_B: h1 writes -> reads

            // ---- GEMM2: full-K from h buffer, N-half of W2 ----
            uint32_t acc2[16][2];
            #pragma unroll
            for (int nf = 0; nf < 16; nf++) {
                uint32_t bh = packh2(*(const float2*)(B2 + 128 * h + 8 * nf + cp));
                acc2[nf][0] = bh; acc2[nf][1] = bh;
            }
            #pragma unroll 2
            for (int p = 0; p < 8; p++) {
                uint4 A0 = hb[(2 * p) * 32];
                uint4 A1 = hb[(2 * p + 1) * 32];
                #pragma unroll
                for (int nf = 0; nf < 16; nf++) {
                    uint4 bb = w2q[(p * 32 + 16 * h + nf) * 32 + l];
                    mma_f16h(acc2[nf], (const uint32_t*)&A0, bb.x, bb.y);
                    mma_f16h(acc2[nf], (const uint32_t*)&A1, bb.z, bb.w);
                }
            }
            __syncthreads();   // S_C: h1 reads done -> h2 writes
            #pragma unroll
            for (int nfp = 0; nfp < 8; nfp++) {
                float2 a0 = unpackh(acc2[2 * nfp][0]);
                float2 a1 = unpackh(acc2[2 * nfp][1]);
                float2 a2 = unpackh(acc2[2 * nfp + 1][0]);
                float2 a3 = unpackh(acc2[2 * nfp + 1][1]);
                uint4 val;
                val.x = packh(silu(a0.x), silu(a0.y));
                val.y = packh(silu(a1.x), silu(a1.y));
                val.z = packh(silu(a2.x), silu(a2.y));
                val.w = packh(silu(a3.x), silu(a3.y));
                hb[(8 * h + nfp) * 32] = val;
            }
            __syncthreads();   // S_D: h2 writes -> reads

            // ---- GEMM3: full-K from h buffer, N-quarter (32 cols) of W3 ----
            uint32_t acc3[4][2];
            #pragma unroll
            for (int nf = 0; nf < 4; nf++) {
                uint32_t bh = packh2(*(const float2*)(B3 + 32 * h + 8 * nf + cp));
                acc3[nf][0] = bh; acc3[nf][1] = bh;
            }
            #pragma unroll 2
            for (int p = 0; p < 8; p++) {
                uint4 A0 = hb[(2 * p) * 32];
                uint4 A1 = hb[(2 * p + 1) * 32];
                #pragma unroll
                for (int nf = 0; nf < 4; nf++) {
                    uint4 bb = w3q[(p * 8 + 4 * h + nf) * 32 + l];
                    mma_f16h(acc3[nf], (const uint32_t*)&A0, bb.x, bb.y);
                    mma_f16h(acc3[nf], (const uint32_t*)&A1, bb.z, bb.w);
                }
            }

            // ---- epilogue ----
            if (st < 5) {
                uint32_t* kw = ktile + st * 4096 + (mrow0 + rl) * 32 + 16 * h + lp;
                #pragma unroll
                for (int nf = 0; nf < 4; nf++) {
                    kw[4 * nf]       = acc3[nf][0];
                    kw[4 * nf + 256] = acc3[nf][1];
                }
            } else {
                const float d5 = DTf * c_Bc[5];
                const long r0 = base + mrow0 + rl;
                const float* ya = obs + r0 * 64 + 32 * h;
                float* oa = out + r0 * 64 + 32 * h;
                const uint32_t* kr = ktile + (mrow0 + rl) * 32 + 16 * h + lp;
                #pragma unroll
                for (int nf = 0; nf < 4; nf++) {
                    float2 y0v = *(const float2*)(ya + 8 * nf + cp);
                    float2 y1v = *(const float2*)(ya + 512 + 8 * nf + cp);
                    float2 k5a = unpackh(acc3[nf][0]);
                    float2 k5b = unpackh(acc3[nf][1]);
                    float o00 = fmaf(d5, k5a.x, y0v.x), o01 = fmaf(d5, k5a.y, y0v.y);
                    float o10 = fmaf(d5, k5b.x, y1v.x), o11 = fmaf(d5, k5b.y, y1v.y);
                    #pragma unroll
                    for (int j = 0; j < 5; j++) {
                        float d = DTf * c_Bc[j];
                        float2 ta = unpackh(kr[j * 4096 + 4 * nf]);
                        float2 tb = unpackh(kr[j * 4096 + 4 * nf + 256]);
                        o00 = fmaf(d, ta.x, o00); o01 = fmaf(d, ta.y, o01);
                        o10 = fmaf(d, tb.x, o10); o11 = fmaf(d, tb.y, o11);
                    }
                    *(float2*)(oa + 8 * nf + cp) = make_float2(o00, o01);
                    *(float2*)(oa + 512 + 8 * nf + cp) = make_float2(o10, o11);
                }
            }
        }
    }
}

extern "C" void kernel_launch(void* const* d_in, const int* in_sizes, int n_in,
                              void* d_out, int out_size)
{
    const float* obs = (const float*)d_in[0];
    const float* act = (const float*)d_in[1];
    const float* W1  = (const float*)d_in[2];
    const float* b1  = (const float*)d_in[3];
    const float* W2  = (const float*)d_in[4];
    const float* b2  = (const float*)d_in[5];
    const float* W3  = (const float*)d_in[6];
    const float* b3  = (const float*)d_in[7];
    float* out = (float*)d_out;

    const int batch  = in_sizes[0] / 64;
    int ntiles = batch / 128;
    if (ntiles > MAXTILES) ntiles = MAXTILES;

    cudaFuncSetAttribute(tsit5_mma_kernel,
                         cudaFuncAttributeMaxDynamicSharedMemorySize, SMEM_BYTES);

    tsit5_mma_kernel<<<GRID, NT, SMEM_BYTES>>>(obs, act, W1, b1, W2, b2, W3, b3, out, ntiles);
}

// round 16
// speedup vs baseline: 1.2367x; 1.2219x over previous
#include <cuda_runtime.h>
#include <cuda_fp16.h>
#include <cstdint>

#define NT    512
#define GRID  148
#define DTf   0.05f
#define MAXTILES 1024

// ---------------- Tsit5 tableau ----------------
__constant__ float c_A[6][5] = {
    {0.f, 0.f, 0.f, 0.f, 0.f},
    {0.161f, 0.f, 0.f, 0.f, 0.f},
    {-0.008480655492356989f, 0.335480655492357f, 0.f, 0.f, 0.f},
    {2.8971530571054935f, -6.359448489975075f, 4.3622954328695815f, 0.f, 0.f},
    {5.325864828439257f, -11.748883564062828f, 7.4955393428898365f, -0.09249506636175525f, 0.f},
    {5.86145544294642f, -12.92096931784711f, 8.159367898576159f, -0.071584973281401f, -0.028269050394068383f},
};
__constant__ float c_Bc[6] = {
    0.09646076681806523f, 0.01f, 0.4798896504144996f,
    1.379008574103742f, -3.290069515436081f, 2.324710524099774f
};

// k scratch: [tile][mw(8)][stage(5)][colpair(32)][row(16)] f16x2 — warp-coalesced blocks
__device__ uint32_t g_k[(size_t)MAXTILES * 8 * 5 * 512];
// W1 B-fragments in global:
//   pairs:   [p(2)][nfg(32)][lane(32)] x 16B = 32768 B
//   singles: [nfg(32)][lane(32)] x 8B        =  8192 B
__device__ __align__(16) unsigned char g_w1c[40960];

// ---------------- SMEM layout (bytes) ----------------
// h buffer (pair-local h1/h2 staging, A-frag layout): [mw(8)][g(16)][lane(32)] x 16B
#define OH   0          // 65536
#define OW2  65536      // [p(8)][nfg(32)][lane] x 16B = 131072
#define OW3  196608     // [p(8)][nfg(8)][lane] x 16B  = 32768
#define OB1  229376     // 256 f32
#define OB2  230400     // 256 f32
#define OB3  231424     // 64 f32
#define SMEM_BYTES 231680

// ---------------- helpers ----------------
__device__ __forceinline__ uint32_t packh(float lo, float hi) {
    uint32_t r; asm("cvt.rn.f16x2.f32 %0, %1, %2;" : "=r"(r) : "f"(hi), "f"(lo)); return r;
}
__device__ __forceinline__ uint32_t packh2(float2 v) { return packh(v.x, v.y); }
__device__ __forceinline__ float2 unpackh(uint32_t v) {
    __half2 h = *reinterpret_cast<__half2*>(&v);
    return __half22float2(h);
}
__device__ __forceinline__ float tanh_fast(float x) {
    float y; asm("tanh.approx.f32 %0, %1;" : "=f"(y) : "f"(x)); return y;
}
__device__ __forceinline__ float silu(float x) {
    float t = tanh_fast(0.5f * x);
    return fmaf(x, 0.5f * t, 0.5f * x);
}
__device__ __forceinline__ void mma_f16h(uint32_t* c, const uint32_t* a, uint32_t b0, uint32_t b1) {
    asm volatile(
        "mma.sync.aligned.m16n8k16.row.col.f16.f16.f16.f16 "
        "{%0,%1},{%2,%3,%4,%5},{%6,%7},{%0,%1};"
        : "+r"(c[0]), "+r"(c[1])
        : "r"(a[0]), "r"(a[1]), "r"(a[2]), "r"(a[3]), "r"(b0), "r"(b1));
}
// pair barrier: warps mw and mw+8 only (64 threads); other pairs drift freely
#define PAIRBAR() asm volatile("bar.sync %0, 64;" :: "r"(mw + 1) : "memory")

extern __shared__ char sm[];

__global__ void __launch_bounds__(NT, 1)
tsit5_mma_kernel(const float* __restrict__ obs, const float* __restrict__ act,
                 const float* __restrict__ gW1, const float* __restrict__ gb1,
                 const float* __restrict__ gW2, const float* __restrict__ gb2,
                 const float* __restrict__ gW3, const float* __restrict__ gb3,
                 float* __restrict__ out, int ntiles)
{
    const int tid = threadIdx.x;

    // ---- weight conversion: W1 -> global frags, W2/W3 -> SMEM frags ----
    for (int idx = tid; idx < 80 * 256; idx += NT) {
        int k = idx >> 8, n = idx & 255;
        int lane = (n & 7) * 4 + ((k & 7) >> 1);
        int kb = (((k >> 3) & 1) << 2) + ((k & 1) << 1);
        int ks = k >> 4, nfg = n >> 3;
        int off = (ks < 4) ? ((((ks >> 1) * 32 + nfg) * 32 + lane) * 16 + (ks & 1) * 8 + kb)
                           : (32768 + (nfg * 32 + lane) * 8 + kb);
        *(__half*)(g_w1c + off) = __float2half(gW1[idx]);
    }
    for (int idx = tid; idx < 256 * 256; idx += NT) {
        int k = idx >> 8, n = idx & 255;
        int lane = (n & 7) * 4 + ((k & 7) >> 1);
        int kb = (((k >> 3) & 1) << 2) + ((k & 1) << 1);
        int ks = k >> 4, p = ks >> 1, nfg = n >> 3;
        *(__half*)(sm + OW2 + ((p * 32 + nfg) * 32 + lane) * 16 + (ks & 1) * 8 + kb) =
            __float2half(gW2[idx]);
    }
    for (int idx = tid; idx < 256 * 64; idx += NT) {
        int k = idx >> 6, n = idx & 63;
        int lane = (n & 7) * 4 + ((k & 7) >> 1);
        int kb = (((k >> 3) & 1) << 2) + ((k & 1) << 1);
        int ks = k >> 4, p = ks >> 1, nfg = n >> 3;
        *(__half*)(sm + OW3 + ((p * 8 + nfg) * 32 + lane) * 16 + (ks & 1) * 8 + kb) =
            __float2half(gW3[idx]);
    }
    for (int i = tid; i < 256; i += NT) {
        ((float*)(sm + OB1))[i] = gb1[i];
        ((float*)(sm + OB2))[i] = gb2[i];
    }
    for (int i = tid; i < 64; i += NT) ((float*)(sm + OB3))[i] = gb3[i];
    __syncthreads();

    const float* B1 = (const float*)(sm + OB1);
    const float* B2 = (const float*)(sm + OB2);
    const float* B3 = (const float*)(sm + OB3);

    const int w  = tid >> 5, l = tid & 31;
    const int h  = w >> 3;           // N-half: 0 -> cols 0-127, 1 -> cols 128-255
    const int mw = w & 7;            // M-group: 16 rows each (pair = warps mw, mw+8)
    const int mrow0 = mw * 16;
    const int rl = l >> 2;
    const int lp = l & 3;
    const int cp = lp * 2;

    const uint4* w1q = (const uint4*)g_w1c;
    const uint2* w1s = (const uint2*)(g_w1c + 32768);
    const uint4* w2q = (const uint4*)(sm + OW2);
    const uint4* w3q = (const uint4*)(sm + OW3);
    uint4* hb = (uint4*)(sm + OH) + mw * 512 + l;   // pair-local 8KB region

    for (int tile = blockIdx.x; tile < ntiles; tile += GRID) {
        const long base = (long)tile * 128;
        // pair-local k block: [stage(5)][colpair(32)][row(16)]
        uint32_t* kmw = g_k + ((size_t)tile * 8 + mw) * 5 * 512;

        // action A-frags (persistent per tile)
        uint32_t xact[4];
        {
            const float* aa = act + (base + mrow0 + rl) * 16;
            xact[0] = packh2(*(const float2*)(aa + cp));
            xact[1] = packh2(*(const float2*)(aa + 128 + cp));
            xact[2] = packh2(*(const float2*)(aa + 8 + cp));
            xact[3] = packh2(*(const float2*)(aa + 128 + 8 + cp));
        }

        #pragma unroll 1
        for (int st = 0; st < 6; st++) {
            PAIRBAR();   // S_A: partner's prev-stage k writes + hb reads complete

            // ---- x-build: fp32 y0 + dt * sum_j a[st][j]*k_j (coalesced k reads) ----
            uint32_t xa[4][4];
            {
                const float* ya = obs + (base + mrow0 + rl) * 64;
                const float* yb = ya + 512;
                #pragma unroll
                for (int ks = 0; ks < 4; ks++) {
                    const uint32_t* krb = kmw + (8 * ks + lp) * 16 + rl;
                    float2 v0 = *(const float2*)(ya + 16 * ks + cp);
                    float2 v1 = *(const float2*)(yb + 16 * ks + cp);
                    float2 v2 = *(const float2*)(ya + 16 * ks + 8 + cp);
                    float2 v3 = *(const float2*)(yb + 16 * ks + 8 + cp);
                    #pragma unroll
                    for (int j = 0; j < 5; j++)
                        if (j < st) {
                            float a = DTf * c_A[st][j];
                            float2 t;
                            t = unpackh(krb[j * 512]);      v0.x = fmaf(a, t.x, v0.x); v0.y = fmaf(a, t.y, v0.y);
                            t = unpackh(krb[j * 512 + 8]);  v1.x = fmaf(a, t.x, v1.x); v1.y = fmaf(a, t.y, v1.y);
                            t = unpackh(krb[j * 512 + 64]); v2.x = fmaf(a, t.x, v2.x); v2.y = fmaf(a, t.y, v2.y);
                            t = unpackh(krb[j * 512 + 72]); v3.x = fmaf(a, t.x, v3.x); v3.y = fmaf(a, t.y, v3.y);
                        }
                    xa[ks][0] = packh2(v0);
                    xa[ks][1] = packh2(v1);
                    xa[ks][2] = packh2(v2);
                    xa[ks][3] = packh2(v3);
                }
            }

            // ---- GEMM1: h1 (16 rows x 128 cols) = silu(X @ W1 + b1) ----
            {
                uint32_t acc1[16][2];
                #pragma unroll
                for (int nf = 0; nf < 16; nf++) {
                    uint32_t bh = packh2(*(const float2*)(B1 + 128 * h + 8 * nf + cp));
                    acc1[nf][0] = bh; acc1[nf][1] = bh;
                }
                #pragma unroll
                for (int p = 0; p < 2; p++)
                    #pragma unroll
                    for (int nf = 0; nf < 16; nf++) {
                        uint4 bb = w1q[(p * 32 + 16 * h + nf) * 32 + l];
                        mma_f16h(acc1[nf], xa[2 * p],     bb.x, bb.y);
                        mma_f16h(acc1[nf], xa[2 * p + 1], bb.z, bb.w);
                    }
                #pragma unroll
                for (int nf = 0; nf < 16; nf++) {
                    uint2 bb = w1s[(16 * h + nf) * 32 + l];
                    mma_f16h(acc1[nf], xact, bb.x, bb.y);
                }
                #pragma unroll
                for (int nfp = 0; nfp < 8; nfp++) {
                    float2 a0 = unpackh(acc1[2 * nfp][0]);
                    float2 a1 = unpackh(acc1[2 * nfp][1]);
                    float2 a2 = unpackh(acc1[2 * nfp + 1][0]);
                    float2 a3 = unpackh(acc1[2 * nfp + 1][1]);
                    uint4 val;
                    val.x = packh(silu(a0.x), silu(a0.y));
                    val.y = packh(silu(a1.x), silu(a1.y));
                    val.z = packh(silu(a2.x), silu(a2.y));
                    val.w = packh(silu(a3.x), silu(a3.y));
                    hb[(8 * h + nfp) * 32] = val;
                }
            }
            PAIRBAR();   // S_B: h1 writes -> reads (pair only)

            // ---- GEMM2: full-K from pair h buffer, N-half of W2 ----
            uint32_t acc2[16][2];
            #pragma unroll
            for (int nf = 0; nf < 16; nf++) {
                uint32_t bh = packh2(*(const float2*)(B2 + 128 * h + 8 * nf + cp));
                acc2[nf][0] = bh; acc2[nf][1] = bh;
            }
            #pragma unroll 2
            for (int p = 0; p < 8; p++) {
                uint4 A0 = hb[(2 * p) * 32];
                uint4 A1 = hb[(2 * p + 1) * 32];
                #pragma unroll
                for (int nf = 0; nf < 16; nf++) {
                    uint4 bb = w2q[(p * 32 + 16 * h + nf) * 32 + l];
                    mma_f16h(acc2[nf], (const uint32_t*)&A0, bb.x, bb.y);
                    mma_f16h(acc2[nf], (const uint32_t*)&A1, bb.z, bb.w);
                }
            }
            PAIRBAR();   // S_C: h1 reads done -> h2 writes
            #pragma unroll
            for (int nfp = 0; nfp < 8; nfp++) {
                float2 a0 = unpackh(acc2[2 * nfp][0]);
                float2 a1 = unpackh(acc2[2 * nfp][1]);
                float2 a2 = unpackh(acc2[2 * nfp + 1][0]);
                float2 a3 = unpackh(acc2[2 * nfp + 1][1]);
                uint4 val;
                val.x = packh(silu(a0.x), silu(a0.y));
                val.y = packh(silu(a1.x), silu(a1.y));
                val.z = packh(silu(a2.x), silu(a2.y));
                val.w = packh(silu(a3.x), silu(a3.y));
                hb[(8 * h + nfp) * 32] = val;
            }
            PAIRBAR();   // S_D: h2 writes -> reads

            // ---- GEMM3: full-K from pair h buffer, N-quarter (32 cols) ----
            uint32_t acc3[4][2];
            #pragma unroll
            for (int nf = 0; nf < 4; nf++) {
                uint32_t bh = packh2(*(const float2*)(B3 + 32 * h + 8 * nf + cp));
                acc3[nf][0] = bh; acc3[nf][1] = bh;
            }
            #pragma unroll 2
            for (int p = 0; p < 8; p++) {
                uint4 A0 = hb[(2 * p) * 32];
                uint4 A1 = hb[(2 * p + 1) * 32];
                #pragma unroll
                for (int nf = 0; nf < 4; nf++) {
                    uint4 bb = w3q[(p * 8 + 4 * h + nf) * 32 + l];
                    mma_f16h(acc3[nf], (const uint32_t*)&A0, bb.x, bb.y);
                    mma_f16h(acc3[nf], (const uint32_t*)&A1, bb.z, bb.w);
                }
            }

            // ---- epilogue (coalesced k writes within pair block) ----
            if (st < 5) {
                uint32_t* kw = kmw + st * 512 + (16 * h + lp) * 16 + rl;
                #pragma unroll
                for (int nf = 0; nf < 4; nf++) {
                    kw[64 * nf]     = acc3[nf][0];
                    kw[64 * nf + 8] = acc3[nf][1];
                }
            } else {
                const float d5 = DTf * c_Bc[5];
                const long r0 = base + mrow0 + rl;
                const float* ya = obs + r0 * 64 + 32 * h;
                float* oa = out + r0 * 64 + 32 * h;
                const uint32_t* krf = kmw + (16 * h + lp) * 16 + rl;
                #pragma unroll
                for (int nf = 0; nf < 4; nf++) {
                    float2 y0v = *(const float2*)(ya + 8 * nf + cp);
                    float2 y1v = *(const float2*)(ya + 512 + 8 * nf + cp);
                    float2 k5a = unpackh(acc3[nf][0]);
                    float2 k5b = unpackh(acc3[nf][1]);
                    float o00 = fmaf(d5, k5a.x, y0v.x), o01 = fmaf(d5, k5a.y, y0v.y);
                    float o10 = fmaf(d5, k5b.x, y1v.x), o11 = fmaf(d5, k5b.y, y1v.y);
                    #pragma unroll
                    for (int j = 0; j < 5; j++) {
                        float d = DTf * c_Bc[j];
                        float2 ta = unpackh(krf[j * 512 + 64 * nf]);
                        float2 tb = unpackh(krf[j * 512 + 64 * nf + 8]);
                        o00 = fmaf(d, ta.x, o00); o01 = fmaf(d, ta.y, o01);
                        o10 = fmaf(d, tb.x, o10); o11 = fmaf(d, tb.y, o11);
                    }
                    *(float2*)(oa + 8 * nf + cp) = make_float2(o00, o01);
                    *(float2*)(oa + 512 + 8 * nf + cp) = make_float2(o10, o11);
                }
            }
        }
    }
}

extern "C" void kernel_launch(void* const* d_in, const int* in_sizes, int n_in,
                              void* d_out, int out_size)
{
    const float* obs = (const float*)d_in[0];
    const float* act = (const float*)d_in[1];
    const float* W1  = (const float*)d_in[2];
    const float* b1  = (const float*)d_in[3];
    const float* W2  = (const float*)d_in[4];
    const float* b2  = (const float*)d_in[5];
    const float* W3  = (const float*)d_in[6];
    const float* b3  = (const float*)d_in[7];
    float* out = (float*)d_out;

    const int batch  = in_sizes[0] / 64;
    int ntiles = batch / 128;
    if (ntiles > MAXTILES) ntiles = MAXTILES;

    cudaFuncSetAttribute(tsit5_mma_kernel,
                         cudaFuncAttributeMaxDynamicSharedMemorySize, SMEM_BYTES);

    tsit5_mma_kernel<<<GRID, NT, SMEM_BYTES>>>(obs, act, W1, b1, W2, b2, W3, b3, out, ntiles);
}